// round 4
// baseline (speedup 1.0000x reference)
#include <cuda_runtime.h>
#include <cuda_fp16.h>
#include <cuda_bf16.h>

#define N_NODES 10000
#define E_EDGES 160000
#define EP (E_EDGES + N_NODES)   // edges + self loops = 170000
#define IN_CH 128
#define EMB 64
#define HEADS 12
#define HD (HEADS * EMB)          // 768
#define NEG_SLOPE 0.2f

// ---- scratch (device globals; no allocation allowed) ----
__device__ float  g_emb[N_NODES * EMB];        // relu(x@We+be)   fp32
__device__ __half g_hh16[N_NODES * HD];        // emb@W, fp16 (only consumer: gather)
__device__ float  g_asrc[N_NODES * HEADS];
__device__ float  g_adst[N_NODES * HEADS];
__device__ float  g_denom[N_NODES * HEADS];
__device__ float  g_invden[N_NODES * HEADS];
__device__ float  g_eexp[EP * HEADS];          // per-edge exp(logit)
__device__ float  g_agg[N_NODES * EMB];        // head-summed weighted msgs

// ---- pass 1: emb = relu(x @ We + be), 16 nodes per block ----
__global__ void __launch_bounds__(64) k_emb(const float* __restrict__ x,
                                            const float* __restrict__ We,
                                            const float* __restrict__ be) {
    __shared__ float sx[IN_CH][16];
    int n0 = blockIdx.x * 16;
    int t = threadIdx.x;                     // 0..63 = output channel
    for (int idx = t; idx < 16 * IN_CH; idx += 64) {
        int i = idx >> 7, k = idx & 127;
        sx[k][i] = x[(n0 + i) * IN_CH + k];
    }
    __syncthreads();
    float acc[16];
    float b = be[t];
#pragma unroll
    for (int i = 0; i < 16; i++) acc[i] = b;
    for (int k = 0; k < IN_CH; k++) {
        float wv = We[k * EMB + t];
#pragma unroll
        for (int i = 0; i < 16; i++) acc[i] += sx[k][i] * wv;
    }
#pragma unroll
    for (int i = 0; i < 16; i++)
        g_emb[(n0 + i) * EMB + t] = fmaxf(acc[i], 0.f);
}

// ---- pass 2: hh = emb @ W (fp16 out) + fp32 per-head logits, 16 nodes/block ----
__global__ void __launch_bounds__(768) k_hh(const float* __restrict__ W,
                                            const float* __restrict__ att_src,
                                            const float* __restrict__ att_dst) {
    __shared__ float se[EMB][16];
    __shared__ float ssrc[16][HEADS];
    __shared__ float sdst[16][HEADS];
    int n0 = blockIdx.x * 16;
    int t = threadIdx.x;                     // 0..767
    for (int idx = t; idx < 16 * EMB; idx += 768) {
        int i = idx >> 6, k = idx & 63;
        se[k][i] = g_emb[(n0 + i) * EMB + k];
    }
    if (t < 16 * HEADS) {
        ((float*)ssrc)[t] = 0.f;
        ((float*)sdst)[t] = 0.f;
    }
    __syncthreads();
    float acc[16];
#pragma unroll
    for (int i = 0; i < 16; i++) acc[i] = 0.f;
    for (int k = 0; k < EMB; k++) {
        float wv = W[k * HD + t];
#pragma unroll
        for (int i = 0; i < 16; i++) acc[i] += se[k][i] * wv;
    }
    float as = att_src[t], ad = att_dst[t];
    int h = t >> 6;                          // constant within each warp
#pragma unroll
    for (int i = 0; i < 16; i++) {
        g_hh16[(size_t)(n0 + i) * HD + t] = __float2half_rn(acc[i]);
        float ps = acc[i] * as;
        float pd = acc[i] * ad;
#pragma unroll
        for (int off = 16; off; off >>= 1) {
            ps += __shfl_down_sync(0xffffffffu, ps, off);
            pd += __shfl_down_sync(0xffffffffu, pd, off);
        }
        if ((t & 31) == 0) {
            atomicAdd(&ssrc[i][h], ps);
            atomicAdd(&sdst[i][h], pd);
        }
    }
    __syncthreads();
    if (t < 16 * HEADS) {
        int i = t / HEADS, hh_ = t % HEADS;
        g_asrc[(n0 + i) * HEADS + hh_] = ssrc[i][hh_];
        g_adst[(n0 + i) * HEADS + hh_] = sdst[i][hh_];
    }
}

// ---- init scratch each launch (graph replays!) ----
__global__ void k_init() {
    int idx = blockIdx.x * blockDim.x + threadIdx.x;
    if (idx < N_NODES * EMB) g_agg[idx] = 0.f;
    if (idx < N_NODES * HEADS) g_denom[idx] = 0.f;
}

// ---- pass 3: per-edge exp(leaky(logit)) (no max needed; |logit| < ~6)
//      + atomic denominator accumulation. One thread per edge. ----
__global__ void k_sum(const int* __restrict__ ei) {
    int e = blockIdx.x * blockDim.x + threadIdx.x;
    if (e >= EP) return;
    int s, d;
    if (e < E_EDGES) { s = ei[e]; d = ei[E_EDGES + e]; }
    else             { s = d = e - E_EDGES; }
    const float4* a4 = (const float4*)g_asrc;
    const float4* b4 = (const float4*)g_adst;
    float4 sa[3] = { a4[s * 3], a4[s * 3 + 1], a4[s * 3 + 2] };
    float4 da[3] = { b4[d * 3], b4[d * 3 + 1], b4[d * 3 + 2] };
    const float* sf = (const float*)sa;
    const float* df = (const float*)da;
    float ex[HEADS];
#pragma unroll
    for (int h = 0; h < HEADS; h++) {
        float v = sf[h] + df[h];
        v = v > 0.f ? v : NEG_SLOPE * v;
        ex[h] = __expf(v);
        atomicAdd(&g_denom[d * HEADS + h], ex[h]);
    }
    float4* e4 = (float4*)g_eexp;
#pragma unroll
    for (int q = 0; q < 3; q++)
        e4[e * 3 + q] = ((const float4*)ex)[q];
}

// ---- pass 3b: reciprocal of denominators ----
__global__ void k_inv() {
    int idx = blockIdx.x * blockDim.x + threadIdx.x;
    if (idx < N_NODES * HEADS)
        g_invden[idx] = 1.f / (g_denom[idx] + 1e-16f);
}

// ---- pass 4: weighted aggregate (head-reduced per edge), 1 warp / edge ----
__global__ void k_agg(const int* __restrict__ ei) {
    int gtid = blockIdx.x * blockDim.x + threadIdx.x;
    int e = gtid >> 5;
    int lane = threadIdx.x & 31;
    if (e >= EP) return;
    int s, d;
    if (e < E_EDGES) { s = ei[e]; d = ei[E_EDGES + e]; }
    else             { s = d = e - E_EDGES; }
    float wl = 0.f;
    if (lane < HEADS)
        wl = g_eexp[e * HEADS + lane] * g_invden[d * HEADS + lane];
    float w[HEADS];
#pragma unroll
    for (int h = 0; h < HEADS; h++) w[h] = __shfl_sync(0xffffffffu, wl, h);
    const __half2* hrow = (const __half2*)(g_hh16 + (size_t)s * HD);
    float m0 = 0.f, m1 = 0.f;
#pragma unroll
    for (int h = 0; h < HEADS; h++) {
        float2 f = __half22float2(hrow[h * 32 + lane]);
        m0 += w[h] * f.x;
        m1 += w[h] * f.y;
    }
    atomicAdd(&g_agg[d * EMB + 2 * lane],     m0);
    atomicAdd(&g_agg[d * EMB + 2 * lane + 1], m1);
}

// ---- pass 5: out = relu(emb + mean_heads(agg) + bias) ----
__global__ void k_final(const float* __restrict__ bias, float* __restrict__ out) {
    int idx = blockIdx.x * blockDim.x + threadIdx.x;
    if (idx >= N_NODES * EMB) return;
    int c = idx & 63;
    out[idx] = fmaxf(g_emb[idx] + g_agg[idx] * (1.f / HEADS) + bias[c], 0.f);
}

extern "C" void kernel_launch(void* const* d_in, const int* in_sizes, int n_in,
                              void* d_out, int out_size) {
    const float* x    = (const float*)d_in[0];
    const int*   ei   = (const int*)d_in[1];
    const float* We   = (const float*)d_in[2];
    const float* be   = (const float*)d_in[3];
    const float* W    = (const float*)d_in[4];
    const float* asrc = (const float*)d_in[5];
    const float* adst = (const float*)d_in[6];
    const float* bias = (const float*)d_in[7];
    float* out = (float*)d_out;

    k_emb<<<N_NODES / 16, 64>>>(x, We, be);
    k_init<<<(N_NODES * EMB + 255) / 256, 256>>>();
    k_hh<<<N_NODES / 16, 768>>>(W, asrc, adst);
    k_sum<<<(EP + 255) / 256, 256>>>(ei);
    k_inv<<<(N_NODES * HEADS + 255) / 256, 256>>>();
    k_agg<<<(EP * 32 + 255) / 256, 256>>>(ei);
    k_final<<<(N_NODES * EMB + 255) / 256, 256>>>(bias, out);
}